// round 14
// baseline (speedup 1.0000x reference)
#include <cuda_runtime.h>
#include <math.h>

// ---------------- dimensions ----------------
#define FF 66
#define FF2 4356
#define FF3 287496
#define HH 33
#define HH2 1089
#define HH3 35937
#define TS 64
#define TS2 4096
#define TS3 262144
#define NG 8

// output regions (element offsets in d_out)
static const size_t OX    = 0;          // x: 1x64x64^3
static const size_t OHELM = 16777216;   // helmholtz: 8x4x66^3
static const size_t OVEL  = 25977088;
static const size_t OVP   = 32268544;
static const size_t OVV   = 38560000;

// ---------------- scratch ----------------
__device__ float g_fpm[NG*64*HH3];
__device__ float g_fpb[NG*64*HH3];
__device__ float g_fnm[NG*64*HH3];
__device__ float g_corr[NG*54*HH3];
__device__ float g_c1[NG*16*HH3];
__device__ float g_ups[NG*16*FF3];
__device__ float g_c2[NG*16*FF3];
__device__ float g_bufA[NG*8*TS3];
__device__ float g_bufB[NG*8*TS3];
__device__ float g_w1t[54*27*16];
__device__ float g_w2t[2*8*27*8];
__device__ double g_part[16*32*2];   // BN stat slots: [ch][slot][{sum,sum2}]
__device__ float g_scale[16];
__device__ float g_shift[16];

// ---------------- weight transposes (+ zero BN slots) ----------------
__global__ void k_wt1(const float* __restrict__ wp, const float* __restrict__ wv)
{
    int idx = blockIdx.x*blockDim.x + threadIdx.x;
    if (idx < 16*32*2) g_part[idx] = 0.0;
    if (idx >= 54*27*16) return;
    int oc = idx & 15;
    int tap = (idx >> 4) % 27;
    int ic = idx / (16*27);
    float v = (oc < 8) ? wp[(oc*54+ic)*27+tap] : wv[((oc-8)*54+ic)*27+tap];
    g_w1t[idx] = v;
}

__global__ void k_wt2(const float* __restrict__ wp, const float* __restrict__ wv)
{
    int idx = blockIdx.x*blockDim.x + threadIdx.x;
    if (idx >= 2*8*27*8) return;
    int oc = idx & 7;
    int tap = (idx >> 3) % 27;
    int ic = (idx / 216) & 7;
    int g = idx / 1728;
    const float* w = g ? wv : wp;
    g_w2t[idx] = w[(oc*8+ic)*27+tap];
}

// ---------------- encoder: dual-output factored form ----------------
__global__ void k_enc2(const float* __restrict__ src, const float* __restrict__ msk,
                       const float* __restrict__ bnd,
                       const float* __restrict__ w, const float* __restrict__ bias,
                       float* __restrict__ dst1, float* __restrict__ dst2)
{
    __shared__ float sw[64*64];
    for (int i = threadIdx.x; i < 4096; i += blockDim.x) sw[i] = w[i];
    __syncthreads();
    int t = blockIdx.x*blockDim.x + threadIdx.x;
    if (t >= NG*HH3) return;
    int n = t / HH3, p = t % HH3;
    int x = p / HH2, y = (p / HH) % HH, z = p % HH;
    int xb = 2*x, yb = 2*y, zb = 2*z;
    int boff = xb*FF2 + yb*FF + zb;

    const float* mp = msk + boff;
    float4 m0 = make_float4(mp[0], mp[1], mp[FF], mp[FF+1]);
    float4 m1 = make_float4(mp[FF2], mp[FF2+1], mp[FF2+FF], mp[FF2+FF+1]);
    float4 bq0, bq1;
    bool has_b = (bnd != nullptr);
    if (has_b){
        const float* bp = bnd + boff;
        bq0 = make_float4(bp[0], bp[1], bp[FF], bp[FF+1]);
        bq1 = make_float4(bp[FF2], bp[FF2+1], bp[FF2+FF], bp[FF2+FF+1]);
    }
    float4 s4[16];
    #pragma unroll
    for (int ic=0; ic<8; ic++){
        const float* sp = src + (size_t)(n*8+ic)*FF3 + boff;
        s4[ic*2]   = make_float4(sp[0], sp[1], sp[FF], sp[FF+1]);
        s4[ic*2+1] = make_float4(sp[FF2], sp[FF2+1], sp[FF2+FF], sp[FF2+FF+1]);
    }
    for (int oc=0; oc<64; oc++){
        const float4* wr = (const float4*)(sw + oc*64);
        float4 p0 = make_float4(0.f,0.f,0.f,0.f);
        float4 p1 = make_float4(0.f,0.f,0.f,0.f);
        #pragma unroll
        for (int i=0;i<16;i+=2){
            float4 qa = wr[i], qb = wr[i+1];
            float4 sa = s4[i], sb = s4[i+1];
            p0.x = fmaf(sa.x,qa.x,p0.x); p0.y = fmaf(sa.y,qa.y,p0.y);
            p0.z = fmaf(sa.z,qa.z,p0.z); p0.w = fmaf(sa.w,qa.w,p0.w);
            p1.x = fmaf(sb.x,qb.x,p1.x); p1.y = fmaf(sb.y,qb.y,p1.y);
            p1.z = fmaf(sb.z,qb.z,p1.z); p1.w = fmaf(sb.w,qb.w,p1.w);
        }
        float bb = bias[oc];
        float am = bb + m0.x*p0.x + m0.y*p0.y + m0.z*p0.z + m0.w*p0.w
                      + m1.x*p1.x + m1.y*p1.y + m1.z*p1.z + m1.w*p1.w;
        dst1[(size_t)(n*64+oc)*HH3 + p] = am;
        if (has_b){
            float ab = bb + bq0.x*p0.x + bq0.y*p0.y + bq0.z*p0.z + bq0.w*p0.w
                          + bq1.x*p1.x + bq1.y*p1.y + bq1.z*p1.z + bq1.w*p1.w;
            dst2[(size_t)(n*64+oc)*HH3 + p] = ab;
        }
    }
}

// ---------------- correlation: 54 channels ----------------
__global__ void k_corr()
{
    int t = blockIdx.x*blockDim.x + threadIdx.x;
    if (t >= NG*HH3) return;
    int n = t / HH3, p = t % HH3;
    int x = p / HH2, y = (p / HH) % HH, z = p % HH;
    const float* fpm = g_fpm + (size_t)n*64*HH3 + p;
    const float* fpb = g_fpb + (size_t)n*64*HH3 + p;
    const float* fnm = g_fnm + (size_t)n*64*HH3 + p;
    int off[9]; bool val[9];
    {
        int s = 0;
        #pragma unroll
        for (int di=-1; di<=1; di++)
            #pragma unroll
            for (int dj=-1; dj<=1; dj++, s++){
                off[s] = di*HH2 + dj*HH;
                val[s] = ((unsigned)(x+di) < HH) && ((unsigned)(y+dj) < HH);
            }
    }
    float dm[9], db[9];
    #pragma unroll
    for (int s=0;s<9;s++){ dm[s]=0.f; db[s]=0.f; }
    #pragma unroll 2
    for (int c=0;c<64;c++){
        size_t cb = (size_t)c*HH3;
        float am = __ldg(fpm + cb);
        float ab = __ldg(fpb + cb);
        #pragma unroll
        for (int s=0;s<9;s++){
            float vn = val[s] ? __ldg(fnm + cb + off[s]) : 0.f;
            dm[s] = fmaf(am, vn, dm[s]);
            db[s] = fmaf(ab, vn, db[s]);
        }
    }
    const float inv = 1.f/64.f;
    #pragma unroll
    for (int k=0;k<3;k++){
        float zm = ((k==0 && z==HH-1)||(k==2 && z==0)) ? 0.f : 1.f;
        #pragma unroll
        for (int s=0;s<9;s++){
            g_corr[(size_t)(n*54 + k*9+s)*HH3 + p]      = dm[s]*inv*zm;
            g_corr[(size_t)(n*54 + 27 + k*9+s)*HH3 + p] = db[s]*inv*zm;
        }
    }
}

// ---------------- conv1: 54 -> 16, z-tiled x4, fused BN stats ----------------
// grid: (77, NG), block 128. t covers 33*33*9=9801 positions.
__global__ void k_conv1z(const float* __restrict__ in, float* __restrict__ out)
{
    int t = blockIdx.x*blockDim.x + threadIdx.x;
    int n = blockIdx.y;
    bool valid = (t < 9801);
    int tz = t % 9;
    int y = (t / 9) % 33;
    int x = t / 297;
    int z0 = tz*4;

    float acc[4][16];
    #pragma unroll
    for (int zt=0;zt<4;zt++)
        #pragma unroll
        for (int oc=0;oc<16;oc++) acc[zt][oc]=0.f;

    if (valid){
        const float* ib = in + (size_t)n*54*HH3;
        for (int ic=0; ic<54; ic++){
            const float* ip = ib + (size_t)ic*HH3;
            const float* wic = g_w1t + ic*27*16;
            #pragma unroll
            for (int dx=0;dx<3;dx++){
                int xi = x+dx-1; if ((unsigned)xi >= 33u) continue;
                #pragma unroll
                for (int dy=0;dy<3;dy++){
                    int yi = y+dy-1; if ((unsigned)yi >= 33u) continue;
                    const float* rp = ip + xi*HH2 + yi*HH;
                    float rr[6];
                    #pragma unroll
                    for (int j=0;j<6;j++){
                        int zz = z0-1+j;
                        rr[j] = ((unsigned)zz < 33u) ? __ldg(rp+zz) : 0.f;
                    }
                    const float4* wq = (const float4*)(wic + (dx*3+dy)*48);
                    #pragma unroll
                    for (int dz=0;dz<3;dz++){
                        float4 w0 = wq[dz*4+0], w1 = wq[dz*4+1], w2 = wq[dz*4+2], w3 = wq[dz*4+3];
                        float wv[16] = {w0.x,w0.y,w0.z,w0.w, w1.x,w1.y,w1.z,w1.w,
                                        w2.x,w2.y,w2.z,w2.w, w3.x,w3.y,w3.z,w3.w};
                        #pragma unroll
                        for (int zt=0;zt<4;zt++){
                            float rv = rr[zt+dz];
                            #pragma unroll
                            for (int oc=0;oc<16;oc++) acc[zt][oc] = fmaf(rv, wv[oc], acc[zt][oc]);
                        }
                    }
                }
            }
        }
        int pbase = x*HH2 + y*HH + z0;
        #pragma unroll
        for (int oc=0;oc<16;oc++){
            float* op = out + (size_t)(n*16+oc)*HH3 + pbase;
            #pragma unroll
            for (int zt=0;zt<4;zt++)
                if (z0+zt < 33) op[zt] = acc[zt][oc];
        }
    }

    // fused BN partial stats (warp reduce -> atomic into slot)
    int lane = threadIdx.x & 31;
    int slot = blockIdx.x & 31;
    int nval = valid ? min(4, 33 - z0) : 0;
    for (int oc=0; oc<16; oc++){
        double s = 0.0, s2 = 0.0;
        #pragma unroll
        for (int zt=0; zt<4; zt++)
            if (zt < nval){ double v = (double)acc[zt][oc]; s += v; s2 += v*v; }
        #pragma unroll
        for (int off=16; off; off>>=1){
            s  += __shfl_down_sync(0xffffffffu, s,  off);
            s2 += __shfl_down_sync(0xffffffffu, s2, off);
        }
        if (lane == 0){
            atomicAdd(&g_part[(oc*32+slot)*2],   s);
            atomicAdd(&g_part[(oc*32+slot)*2+1], s2);
        }
    }
}

// ---------------- conv2: grouped 2 x (8->8), DIM=66, z-tiled x4, fused BN stats ----------------
// grid: (579, NG*2), block 128. t covers 66*66*17=74052 positions. blockIdx.y = n*2+g.
__global__ void k_conv2z(const float* __restrict__ in, float* __restrict__ out)
{
    int t = blockIdx.x*blockDim.x + threadIdx.x;
    int n = blockIdx.y >> 1;
    int g = blockIdx.y & 1;
    bool valid = (t < 74052);
    int tz = t % 17;
    int y = (t / 17) % 66;
    int x = t / 1122;
    int z0 = tz*4;

    float acc[4][8];
    #pragma unroll
    for (int zt=0;zt<4;zt++)
        #pragma unroll
        for (int oc=0;oc<8;oc++) acc[zt][oc]=0.f;

    if (valid){
        const float* ib = in + (size_t)(n*16 + g*8)*FF3;
        const float* wg = g_w2t + g*(8*27*8);
        #pragma unroll
        for (int ic=0; ic<8; ic++){
            const float* ip = ib + (size_t)ic*FF3;
            const float* wic = wg + ic*27*8;
            #pragma unroll
            for (int dx=0;dx<3;dx++){
                int xi = x+dx-1; if ((unsigned)xi >= 66u) continue;
                #pragma unroll
                for (int dy=0;dy<3;dy++){
                    int yi = y+dy-1; if ((unsigned)yi >= 66u) continue;
                    const float* rp = ip + xi*FF2 + yi*FF;
                    float rr[6];
                    #pragma unroll
                    for (int j=0;j<6;j++){
                        int zz = z0-1+j;
                        rr[j] = ((unsigned)zz < 66u) ? __ldg(rp+zz) : 0.f;
                    }
                    const float4* wq = (const float4*)(wic + (dx*3+dy)*24);
                    #pragma unroll
                    for (int dz=0;dz<3;dz++){
                        float4 w0 = wq[dz*2+0], w1 = wq[dz*2+1];
                        float wv[8] = {w0.x,w0.y,w0.z,w0.w, w1.x,w1.y,w1.z,w1.w};
                        #pragma unroll
                        for (int zt=0;zt<4;zt++){
                            float rv = rr[zt+dz];
                            #pragma unroll
                            for (int oc=0;oc<8;oc++) acc[zt][oc] = fmaf(rv, wv[oc], acc[zt][oc]);
                        }
                    }
                }
            }
        }
        int pbase = x*FF2 + y*FF + z0;
        #pragma unroll
        for (int oc=0;oc<8;oc++){
            float* op = out + (size_t)(n*16 + g*8 + oc)*FF3 + pbase;
            #pragma unroll
            for (int zt=0;zt<4;zt++)
                if (z0+zt < 66) op[zt] = acc[zt][oc];
        }
    }

    // fused BN partial stats
    int lane = threadIdx.x & 31;
    int slot = blockIdx.x & 31;
    int nval = valid ? min(4, 66 - z0) : 0;
    for (int oc=0; oc<8; oc++){
        double s = 0.0, s2 = 0.0;
        #pragma unroll
        for (int zt=0; zt<4; zt++)
            if (zt < nval){ double v = (double)acc[zt][oc]; s += v; s2 += v*v; }
        #pragma unroll
        for (int off=16; off; off>>=1){
            s  += __shfl_down_sync(0xffffffffu, s,  off);
            s2 += __shfl_down_sync(0xffffffffu, s2, off);
        }
        if (lane == 0){
            int c = g*8 + oc;
            atomicAdd(&g_part[(c*32+slot)*2],   s);
            atomicAdd(&g_part[(c*32+slot)*2+1], s2);
        }
    }
}

// ---------------- BN finalize (reads slots, then zeroes them for reuse) ----------------
__global__ void k_bnfin(const float* __restrict__ g1, const float* __restrict__ b1,
                        const float* __restrict__ g2, const float* __restrict__ b2, int S)
{
    int c = threadIdx.x;
    if (c >= 16) return;
    double s = 0.0, s2 = 0.0;
    for (int k=0;k<32;k++){
        s  += g_part[(c*32+k)*2];
        s2 += g_part[(c*32+k)*2+1];
        g_part[(c*32+k)*2]   = 0.0;
        g_part[(c*32+k)*2+1] = 0.0;
    }
    double cnt = (double)NG * (double)S;
    double mean = s/cnt;
    double var = s2/cnt - mean*mean;
    float gg = (c < 8) ? g1[c] : g2[c-8];
    float bb = (c < 8) ? b1[c] : b2[c-8];
    float sc = gg * rsqrtf((float)var + 1e-5f);
    g_scale[c] = sc;
    g_shift[c] = bb - (float)mean * sc;
}

// ---------------- BN+ReLU fused into 2x trilinear upsample (16ch) ----------------
__global__ void k_upsample(const float* __restrict__ in, float* __restrict__ out)
{
    long long t = (long long)blockIdx.x*blockDim.x + threadIdx.x;
    if (t >= (long long)NG*16*FF3) return;
    int nc = (int)(t / FF3), p = (int)(t % FF3);
    int c = nc & 15;
    int X = p / FF2, Y = (p / FF) % FF, Z = p % FF;
    const float step = 32.0f/65.0f;
    float sx = X*step; int x0 = (int)floorf(sx); float wx = sx - (float)x0; int x1 = min(x0+1, 32);
    float sy = Y*step; int y0 = (int)floorf(sy); float wy = sy - (float)y0; int y1 = min(y0+1, 32);
    float sz = Z*step; int z0 = (int)floorf(sz); float wz = sz - (float)z0; int z1 = min(z0+1, 32);
    float sc = g_scale[c], sh = g_shift[c];
    const float* ip = in + (size_t)nc*HH3;
    #define RD(a,b,cc) fmaxf(__ldg(ip+(a)*HH2+(b)*HH+(cc))*sc+sh, 0.f)
    float c00 = RD(x0,y0,z0)*(1.f-wx) + RD(x1,y0,z0)*wx;
    float c10 = RD(x0,y1,z0)*(1.f-wx) + RD(x1,y1,z0)*wx;
    float c01 = RD(x0,y0,z1)*(1.f-wx) + RD(x1,y0,z1)*wx;
    float c11 = RD(x0,y1,z1)*(1.f-wx) + RD(x1,y1,z1)*wx;
    #undef RD
    float a0 = c00*(1.f-wy) + c10*wy;
    float a1 = c01*(1.f-wy) + c11*wy;
    out[t] = a0*(1.f-wz) + a1*wz;
}

// ---------------- merged head: BN+ReLU + both 1x1 convs ----------------
__global__ void k_head(const float* __restrict__ c2,
                       const float* __restrict__ wphi, const float* __restrict__ bphi,
                       const float* __restrict__ wvort, const float* __restrict__ bvort,
                       const float* __restrict__ phiw, const float* __restrict__ vortw,
                       float* __restrict__ helm)
{
    int t = blockIdx.x*blockDim.x + threadIdx.x;
    if (t >= NG*FF3) return;
    int n = t / FF3, p = t % FF3;
    float r[16];
    #pragma unroll
    for (int ic=0; ic<16; ic++){
        float vv = c2[(size_t)(n*16+ic)*FF3 + p]*g_scale[ic] + g_shift[ic];
        r[ic] = fmaxf(vv, 0.f);
    }
    float mp = phiw[0];
    float mv = vortw[0]*66.0f;
    {
        float a = bphi[0];
        #pragma unroll
        for (int ic=0; ic<8; ic++) a = fmaf(r[ic], wphi[ic], a);
        helm[(size_t)(n*4)*FF3 + p] = a*mp;
    }
    #pragma unroll
    for (int oc=0; oc<3; oc++){
        float a = bvort[oc];
        #pragma unroll
        for (int ic=0; ic<8; ic++) a = fmaf(r[8+ic], wvort[oc*8+ic], a);
        helm[(size_t)(n*4+1+oc)*FF3 + p] = a*mv;
    }
}

// ---------------- velocity from helmholtz ----------------
__global__ void k_velocity(const float* __restrict__ helm, float* __restrict__ vel,
                           float* __restrict__ vp, float* __restrict__ vv)
{
    int t = blockIdx.x*blockDim.x + threadIdx.x;
    if (t >= NG*TS3) return;
    int n = t / TS3, p = t % TS3;
    int x = p >> 12, y = (p >> 6) & 63, z = p & 63;
    const float* phi = helm + (size_t)n*4*FF3;
    const float* s0 = phi + FF3;
    const float* s1 = phi + 2*FF3;
    const float* s2 = phi + 3*FF3;
    int X = x+1, Y = y+1, Z = z+1;
    #define IX(i,j,k) ((i)*FF2+(j)*FF+(k))
    float pu = 0.5f*(phi[IX(X,Y,z+2)] - phi[IX(X,Y,z)]);
    float pv = 0.5f*(phi[IX(X,y+2,Z)] - phi[IX(X,y,Z)]);
    float pw = 0.5f*(phi[IX(x+2,Y,Z)] - phi[IX(x,Y,Z)]);
    float u1 = (s1[IX(X+1,Y,Z)]-s1[IX(X,Y,Z)]) - (s0[IX(X,Y+1,Z)]-s0[IX(X,Y,Z)]);
    float u0 = (s1[IX(X+1,Y,z)]-s1[IX(X,Y,z)]) - (s0[IX(X,Y+1,z)]-s0[IX(X,Y,z)]);
    float vu = 0.5f*(u1+u0);
    float vA = (s0[IX(X,Y,Z+1)]-s0[IX(X,Y,Z)]) - (s2[IX(X+1,Y,Z)]-s2[IX(X,Y,Z)]);
    float vB = (s0[IX(X,y,Z+1)]-s0[IX(X,y,Z)]) - (s2[IX(X+1,y,Z)]-s2[IX(X,y,Z)]);
    float vvm = 0.5f*(vA+vB);
    float wA = (s2[IX(X,Y+1,Z)]-s2[IX(X,Y,Z)]) - (s1[IX(X,Y,Z+1)]-s1[IX(X,Y,Z)]);
    float wB = (s2[IX(x,Y+1,Z)]-s2[IX(x,Y,Z)]) - (s1[IX(x,Y,Z+1)]-s1[IX(x,Y,Z)]);
    float vw = 0.5f*(wA+wB);
    #undef IX
    size_t o = (size_t)n*3*TS3 + p;
    vp[o] = pu;          vp[o+TS3] = pv;          vp[o+2*TS3] = pw;
    vv[o] = vu;          vv[o+TS3] = vvm;         vv[o+2*TS3] = vw;
    vel[o] = pu+vu;      vel[o+TS3] = pv+vvm;     vel[o+2*TS3] = pw+vw;
}

// ---------------- advection (optionally fused with BFECC combine) ----------------
// texc == nullptr : dst = sample(src, back-trace)
// texc != nullptr : dst = 1.5*texc - 0.5*sample(src, back-trace)
__global__ void k_advect(const float* __restrict__ src, const float* __restrict__ vel,
                         float sign, const float* __restrict__ texc,
                         float* __restrict__ dst)
{
    int t = blockIdx.x*blockDim.x + threadIdx.x;
    if (t >= NG*TS3) return;
    int n = t / TS3, p = t % TS3;
    int x = p >> 12, y = (p >> 6) & 63, z = p & 63;
    size_t vb = (size_t)n*3*TS3 + p;
    float px = (float)x - sign*__ldg(vel + vb + 2*TS3);
    float py = (float)y - sign*__ldg(vel + vb + TS3);
    float pz = (float)z - sign*__ldg(vel + vb);
    px = fminf(fmaxf(px, 0.f), 63.f);
    py = fminf(fmaxf(py, 0.f), 63.f);
    pz = fminf(fmaxf(pz, 0.f), 63.f);
    int x0 = (int)floorf(px); float fx = px - (float)x0; int x1 = min(x0+1, 63);
    int y0 = (int)floorf(py); float fy = py - (float)y0; int y1 = min(y0+1, 63);
    int z0 = (int)floorf(pz); float fz = pz - (float)z0; int z1 = min(z0+1, 63);
    int b000 = (x0*64+y0)*64+z0;
    int dxo = (x1-x0)*4096, dyo = (y1-y0)*64, dzo = z1-z0;
    float w000 = (1.f-fx)*(1.f-fy)*(1.f-fz);
    float w001 = (1.f-fx)*(1.f-fy)*fz;
    float w010 = (1.f-fx)*fy*(1.f-fz);
    float w011 = (1.f-fx)*fy*fz;
    float w100 = fx*(1.f-fy)*(1.f-fz);
    float w101 = fx*(1.f-fy)*fz;
    float w110 = fx*fy*(1.f-fz);
    float w111 = fx*fy*fz;
    bool comb = (texc != nullptr);
    #pragma unroll
    for (int c=0; c<8; c++){
        size_t cbase = (size_t)(n*8+c)*TS3;
        const float* s = src + cbase;
        float r = __ldg(s+b000)*w000 + __ldg(s+b000+dzo)*w001
                + __ldg(s+b000+dyo)*w010 + __ldg(s+b000+dyo+dzo)*w011
                + __ldg(s+b000+dxo)*w100 + __ldg(s+b000+dxo+dzo)*w101
                + __ldg(s+b000+dxo+dyo)*w110 + __ldg(s+b000+dxo+dyo+dzo)*w111;
        if (comb) r = 1.5f*__ldg(texc + cbase + p) - 0.5f*r;
        dst[cbase + p] = r;
    }
}

// ---------------- LayerNorm + FFN(GELU) + residual ----------------
__global__ void k_lnffn(const float* __restrict__ pred, const float* __restrict__ lng,
                        const float* __restrict__ lnb, const float* __restrict__ w1,
                        const float* __restrict__ b1, const float* __restrict__ w2,
                        const float* __restrict__ b2, float* __restrict__ xout)
{
    __shared__ float sW1t[64*64];   // [j][i] : lng[i]*W1[i][j]
    __shared__ float sW2t[64*64];   // [c][j] : W2[j][c]
    __shared__ float sc1[64], sSg[64], sb2s[64];
    int tid = threadIdx.x;
    for (int idx = tid; idx < 4096; idx += blockDim.x){
        int r = idx >> 6, c = idx & 63;
        sW1t[c*64+r] = lng[r]*w1[idx];
        sW2t[c*64+r] = w2[idx];
    }
    __syncthreads();
    if (tid < 64){
        int j = tid;
        float a = 0.f, s = 0.f;
        for (int i=0;i<64;i++){ a += lnb[i]*w1[i*64+j]; s += sW1t[j*64+i]; }
        sc1[j] = b1[j]+a; sSg[j] = s; sb2s[j] = b2[j];
    }
    __syncthreads();
    int p = blockIdx.x*blockDim.x + tid;
    float v[64];
    float sum = 0.f;
    #pragma unroll
    for (int c=0;c<64;c++){ v[c] = pred[(size_t)c*TS3 + p]; sum += v[c]; }
    float mean = sum*(1.f/64.f);
    float s2 = 0.f;
    #pragma unroll
    for (int c=0;c<64;c++){ float d = v[c]-mean; s2 = fmaf(d,d,s2); }
    float rstd = rsqrtf(s2*(1.f/64.f) + 1e-5f);
    float h2r[64];
    for (int j=0;j<64;j++){
        const float4* wr = (const float4*)(sW1t + j*64);
        float a0=0.f,a1=0.f,a2=0.f,a3=0.f;
        #pragma unroll
        for (int i=0;i<16;i+=4){
            float4 q0 = wr[i], q1 = wr[i+1], q2 = wr[i+2], q3 = wr[i+3];
            a0 += v[4*i+0]*q0.x + v[4*i+1]*q0.y + v[4*i+2]*q0.z + v[4*i+3]*q0.w;
            a1 += v[4*i+4]*q1.x + v[4*i+5]*q1.y + v[4*i+6]*q1.z + v[4*i+7]*q1.w;
            a2 += v[4*i+8]*q2.x + v[4*i+9]*q2.y + v[4*i+10]*q2.z + v[4*i+11]*q2.w;
            a3 += v[4*i+12]*q3.x + v[4*i+13]*q3.y + v[4*i+14]*q3.z + v[4*i+15]*q3.w;
        }
        float a = (a0+a1)+(a2+a3);
        float tt = rstd*a + sc1[j] - mean*rstd*sSg[j];
        h2r[j] = 0.5f*tt*(1.f + erff(tt*0.70710678118654752f));
    }
    for (int c=0;c<64;c++){
        const float4* wr = (const float4*)(sW2t + c*64);
        float a0=0.f,a1=0.f,a2=0.f,a3=0.f;
        #pragma unroll
        for (int i=0;i<16;i+=4){
            float4 q0 = wr[i], q1 = wr[i+1], q2 = wr[i+2], q3 = wr[i+3];
            a0 += h2r[4*i+0]*q0.x + h2r[4*i+1]*q0.y + h2r[4*i+2]*q0.z + h2r[4*i+3]*q0.w;
            a1 += h2r[4*i+4]*q1.x + h2r[4*i+5]*q1.y + h2r[4*i+6]*q1.z + h2r[4*i+7]*q1.w;
            a2 += h2r[4*i+8]*q2.x + h2r[4*i+9]*q2.y + h2r[4*i+10]*q2.z + h2r[4*i+11]*q2.w;
            a3 += h2r[4*i+12]*q3.x + h2r[4*i+13]*q3.y + h2r[4*i+14]*q3.z + h2r[4*i+15]*q3.w;
        }
        xout[(size_t)c*TS3 + p] = v[c] + (a0+a1)+(a2+a3) + sb2s[c];
    }
}

// ---------------- host launch ----------------
static inline int nb(long long n, int b){ return (int)((n + b - 1) / b); }

extern "C" void kernel_launch(void* const* d_in, const int* in_sizes, int n_in,
                              void* d_out, int out_size)
{
    const float* prev      = (const float*)d_in[0];
    const float* nxt       = (const float*)d_in[1];
    const float* tex       = (const float*)d_in[2];
    const float* mask      = (const float*)d_in[3];
    const float* boundary  = (const float*)d_in[4];
    const float* enc_w     = (const float*)d_in[5];
    const float* enc_b     = (const float*)d_in[6];
    const float* phi_c1_w  = (const float*)d_in[7];
    const float* phi_bn1_g = (const float*)d_in[8];
    const float* phi_bn1_b = (const float*)d_in[9];
    const float* phi_c2_w  = (const float*)d_in[10];
    const float* phi_bn2_g = (const float*)d_in[11];
    const float* phi_bn2_b = (const float*)d_in[12];
    const float* phi_out_w = (const float*)d_in[13];
    const float* phi_out_b = (const float*)d_in[14];
    const float* vort_c1_w = (const float*)d_in[15];
    const float* vort_bn1_g= (const float*)d_in[16];
    const float* vort_bn1_b= (const float*)d_in[17];
    const float* vort_c2_w = (const float*)d_in[18];
    const float* vort_bn2_g= (const float*)d_in[19];
    const float* vort_bn2_b= (const float*)d_in[20];
    const float* vort_out_w= (const float*)d_in[21];
    const float* vort_out_b= (const float*)d_in[22];
    const float* phi_weight= (const float*)d_in[23];
    const float* vort_weight=(const float*)d_in[24];
    const float* ln_g      = (const float*)d_in[25];
    const float* ln_b      = (const float*)d_in[26];
    const float* ff_w1     = (const float*)d_in[27];
    const float* ff_b1     = (const float*)d_in[28];
    const float* ff_w2     = (const float*)d_in[29];
    const float* ff_b2     = (const float*)d_in[30];
    float* out = (float*)d_out;

    float *fpm,*fpb,*fnm,*corr,*c1,*ups,*c2,*bufA,*bufB;
    cudaGetSymbolAddress((void**)&fpm,  g_fpm);
    cudaGetSymbolAddress((void**)&fpb,  g_fpb);
    cudaGetSymbolAddress((void**)&fnm,  g_fnm);
    cudaGetSymbolAddress((void**)&corr, g_corr);
    cudaGetSymbolAddress((void**)&c1,   g_c1);
    cudaGetSymbolAddress((void**)&ups,  g_ups);
    cudaGetSymbolAddress((void**)&c2,   g_c2);
    cudaGetSymbolAddress((void**)&bufA, g_bufA);
    cudaGetSymbolAddress((void**)&bufB, g_bufB);

    // weight transposes (+ zero BN stat slots)
    k_wt1<<<nb(54*27*16,128),128>>>(phi_c1_w, vort_c1_w);
    k_wt2<<<nb(2*8*27*8,128),128>>>(phi_c2_w, vort_c2_w);

    // encoders (prev does mask+boundary in one pass)
    k_enc2<<<nb(NG*HH3,128),128>>>(prev, mask, boundary, enc_w, enc_b, fpm, fpb);
    k_enc2<<<nb(NG*HH3,128),128>>>(nxt,  mask, nullptr,  enc_w, enc_b, fnm, nullptr);

    // correlation
    k_corr<<<nb(NG*HH3,128),128>>>();

    // conv1 (54->16 merged, fused BN1 stats), BN1 finalize, upsample
    k_conv1z<<<dim3(nb(9801,128), NG),128>>>(corr, c1);
    k_bnfin<<<1,16>>>(phi_bn1_g, phi_bn1_b, vort_bn1_g, vort_bn1_b, HH3);
    k_upsample<<<nb((long long)NG*16*FF3,256),256>>>(c1, ups);

    // conv2 (grouped 2x 8->8, fused BN2 stats), BN2 finalize, head
    k_conv2z<<<dim3(nb(74052,128), NG*2),128>>>(ups, c2);
    k_bnfin<<<1,16>>>(phi_bn2_g, phi_bn2_b, vort_bn2_g, vort_bn2_b, FF3);
    k_head<<<nb(NG*FF3,256),256>>>(c2, phi_out_w, phi_out_b, vort_out_w, vort_out_b,
                                   phi_weight, vort_weight, out+OHELM);

    // velocities
    k_velocity<<<nb(NG*TS3,256),256>>>(out+OHELM, out+OVEL, out+OVP, out+OVV);

    // BFECC (combine fused into 2nd advect)
    k_advect<<<nb(NG*TS3,256),256>>>(tex,  out+OVEL,  1.0f, nullptr, bufA);  // phi1
    k_advect<<<nb(NG*TS3,256),256>>>(bufA, out+OVEL, -1.0f, tex,     bufB);  // 1.5 tex - 0.5 phi2
    k_advect<<<nb(NG*TS3,256),256>>>(bufB, out+OVEL,  1.0f, nullptr, bufA);  // pred

    // LN + FFN + residual
    k_lnffn<<<2048,128>>>(bufA, ln_g, ln_b, ff_w1, ff_b1, ff_w2, ff_b2, out+OX);
}

// round 16
// speedup vs baseline: 1.0530x; 1.0530x over previous
#include <cuda_runtime.h>
#include <math.h>

// ---------------- dimensions ----------------
#define FF 66
#define FF2 4356
#define FF3 287496
#define HH 33
#define HH2 1089
#define HH3 35937
#define TS 64
#define TS2 4096
#define TS3 262144
#define NG 8

// output regions (element offsets in d_out)
static const size_t OX    = 0;          // x: 1x64x64^3
static const size_t OHELM = 16777216;   // helmholtz: 8x4x66^3
static const size_t OVEL  = 25977088;
static const size_t OVP   = 32268544;
static const size_t OVV   = 38560000;

// ---------------- scratch ----------------
__device__ float g_fpm[NG*64*HH3];
__device__ float g_fpb[NG*64*HH3];
__device__ float g_fnm[NG*64*HH3];
__device__ float g_corr[NG*54*HH3];
__device__ float g_c1[NG*16*HH3];
__device__ float g_ups[NG*16*FF3];
__device__ float g_c2[NG*16*FF3];
__device__ float g_bufA[NG*8*TS3];
__device__ float g_bufB[NG*8*TS3];
__device__ float g_w1t[54*27*16];
__device__ float g_w2t[2*8*27*8];
__device__ double g_part[16*32*2];
__device__ float g_scale[16];
__device__ float g_shift[16];

// ---------------- weight transposes ----------------
__global__ void k_wt1(const float* __restrict__ wp, const float* __restrict__ wv)
{
    int idx = blockIdx.x*blockDim.x + threadIdx.x;
    if (idx >= 54*27*16) return;
    int oc = idx & 15;
    int tap = (idx >> 4) % 27;
    int ic = idx / (16*27);
    float v = (oc < 8) ? wp[(oc*54+ic)*27+tap] : wv[((oc-8)*54+ic)*27+tap];
    g_w1t[idx] = v;
}

__global__ void k_wt2(const float* __restrict__ wp, const float* __restrict__ wv)
{
    int idx = blockIdx.x*blockDim.x + threadIdx.x;
    if (idx >= 2*8*27*8) return;
    int oc = idx & 7;
    int tap = (idx >> 3) % 27;
    int ic = (idx / 216) & 7;
    int g = idx / 1728;
    const float* w = g ? wv : wp;
    g_w2t[idx] = w[(oc*8+ic)*27+tap];
}

// ---------------- encoder: dual-output factored form ----------------
__global__ void k_enc2(const float* __restrict__ src, const float* __restrict__ msk,
                       const float* __restrict__ bnd,
                       const float* __restrict__ w, const float* __restrict__ bias,
                       float* __restrict__ dst1, float* __restrict__ dst2)
{
    __shared__ float sw[64*64];
    for (int i = threadIdx.x; i < 4096; i += blockDim.x) sw[i] = w[i];
    __syncthreads();
    int t = blockIdx.x*blockDim.x + threadIdx.x;
    if (t >= NG*HH3) return;
    int n = t / HH3, p = t % HH3;
    int x = p / HH2, y = (p / HH) % HH, z = p % HH;
    int xb = 2*x, yb = 2*y, zb = 2*z;
    int boff = xb*FF2 + yb*FF + zb;

    const float* mp = msk + boff;
    float4 m0 = make_float4(mp[0], mp[1], mp[FF], mp[FF+1]);
    float4 m1 = make_float4(mp[FF2], mp[FF2+1], mp[FF2+FF], mp[FF2+FF+1]);
    float4 bq0, bq1;
    bool has_b = (bnd != nullptr);
    if (has_b){
        const float* bp = bnd + boff;
        bq0 = make_float4(bp[0], bp[1], bp[FF], bp[FF+1]);
        bq1 = make_float4(bp[FF2], bp[FF2+1], bp[FF2+FF], bp[FF2+FF+1]);
    }
    float4 s4[16];
    #pragma unroll
    for (int ic=0; ic<8; ic++){
        const float* sp = src + (size_t)(n*8+ic)*FF3 + boff;
        s4[ic*2]   = make_float4(sp[0], sp[1], sp[FF], sp[FF+1]);
        s4[ic*2+1] = make_float4(sp[FF2], sp[FF2+1], sp[FF2+FF], sp[FF2+FF+1]);
    }
    for (int oc=0; oc<64; oc++){
        const float4* wr = (const float4*)(sw + oc*64);
        float4 p0 = make_float4(0.f,0.f,0.f,0.f);
        float4 p1 = make_float4(0.f,0.f,0.f,0.f);
        #pragma unroll
        for (int i=0;i<16;i+=2){
            float4 qa = wr[i], qb = wr[i+1];
            float4 sa = s4[i], sb = s4[i+1];
            p0.x = fmaf(sa.x,qa.x,p0.x); p0.y = fmaf(sa.y,qa.y,p0.y);
            p0.z = fmaf(sa.z,qa.z,p0.z); p0.w = fmaf(sa.w,qa.w,p0.w);
            p1.x = fmaf(sb.x,qb.x,p1.x); p1.y = fmaf(sb.y,qb.y,p1.y);
            p1.z = fmaf(sb.z,qb.z,p1.z); p1.w = fmaf(sb.w,qb.w,p1.w);
        }
        float bb = bias[oc];
        float am = bb + m0.x*p0.x + m0.y*p0.y + m0.z*p0.z + m0.w*p0.w
                      + m1.x*p1.x + m1.y*p1.y + m1.z*p1.z + m1.w*p1.w;
        dst1[(size_t)(n*64+oc)*HH3 + p] = am;
        if (has_b){
            float ab = bb + bq0.x*p0.x + bq0.y*p0.y + bq0.z*p0.z + bq0.w*p0.w
                          + bq1.x*p1.x + bq1.y*p1.y + bq1.z*p1.z + bq1.w*p1.w;
            dst2[(size_t)(n*64+oc)*HH3 + p] = ab;
        }
    }
}

// ---------------- correlation: 54 channels ----------------
__global__ void k_corr()
{
    int t = blockIdx.x*blockDim.x + threadIdx.x;
    if (t >= NG*HH3) return;
    int n = t / HH3, p = t % HH3;
    int x = p / HH2, y = (p / HH) % HH, z = p % HH;
    const float* fpm = g_fpm + (size_t)n*64*HH3 + p;
    const float* fpb = g_fpb + (size_t)n*64*HH3 + p;
    const float* fnm = g_fnm + (size_t)n*64*HH3 + p;
    int off[9]; bool val[9];
    {
        int s = 0;
        #pragma unroll
        for (int di=-1; di<=1; di++)
            #pragma unroll
            for (int dj=-1; dj<=1; dj++, s++){
                off[s] = di*HH2 + dj*HH;
                val[s] = ((unsigned)(x+di) < HH) && ((unsigned)(y+dj) < HH);
            }
    }
    float dm[9], db[9];
    #pragma unroll
    for (int s=0;s<9;s++){ dm[s]=0.f; db[s]=0.f; }
    #pragma unroll 2
    for (int c=0;c<64;c++){
        size_t cb = (size_t)c*HH3;
        float am = __ldg(fpm + cb);
        float ab = __ldg(fpb + cb);
        #pragma unroll
        for (int s=0;s<9;s++){
            float vn = val[s] ? __ldg(fnm + cb + off[s]) : 0.f;
            dm[s] = fmaf(am, vn, dm[s]);
            db[s] = fmaf(ab, vn, db[s]);
        }
    }
    const float inv = 1.f/64.f;
    #pragma unroll
    for (int k=0;k<3;k++){
        float zm = ((k==0 && z==HH-1)||(k==2 && z==0)) ? 0.f : 1.f;
        #pragma unroll
        for (int s=0;s<9;s++){
            g_corr[(size_t)(n*54 + k*9+s)*HH3 + p]      = dm[s]*inv*zm;
            g_corr[(size_t)(n*54 + 27 + k*9+s)*HH3 + p] = db[s]*inv*zm;
        }
    }
}

// ---------------- conv1: 54 -> 16, z-tiled x4 (no BN epilogue) ----------------
// grid: (77, NG), block 128. t covers 33*33*9=9801 positions.
__global__ void k_conv1z(const float* __restrict__ in, float* __restrict__ out)
{
    int t = blockIdx.x*blockDim.x + threadIdx.x;
    int n = blockIdx.y;
    if (t >= 9801) return;
    int tz = t % 9;
    int y = (t / 9) % 33;
    int x = t / 297;
    int z0 = tz*4;

    float acc[4][16];
    #pragma unroll
    for (int zt=0;zt<4;zt++)
        #pragma unroll
        for (int oc=0;oc<16;oc++) acc[zt][oc]=0.f;

    const float* ib = in + (size_t)n*54*HH3;
    for (int ic=0; ic<54; ic++){
        const float* ip = ib + (size_t)ic*HH3;
        const float* wic = g_w1t + ic*27*16;
        #pragma unroll
        for (int dx=0;dx<3;dx++){
            int xi = x+dx-1; if ((unsigned)xi >= 33u) continue;
            #pragma unroll
            for (int dy=0;dy<3;dy++){
                int yi = y+dy-1; if ((unsigned)yi >= 33u) continue;
                const float* rp = ip + xi*HH2 + yi*HH;
                float rr[6];
                #pragma unroll
                for (int j=0;j<6;j++){
                    int zz = z0-1+j;
                    rr[j] = ((unsigned)zz < 33u) ? __ldg(rp+zz) : 0.f;
                }
                const float4* wq = (const float4*)(wic + (dx*3+dy)*48);
                #pragma unroll
                for (int dz=0;dz<3;dz++){
                    float4 w0 = wq[dz*4+0], w1 = wq[dz*4+1], w2 = wq[dz*4+2], w3 = wq[dz*4+3];
                    float wv[16] = {w0.x,w0.y,w0.z,w0.w, w1.x,w1.y,w1.z,w1.w,
                                    w2.x,w2.y,w2.z,w2.w, w3.x,w3.y,w3.z,w3.w};
                    #pragma unroll
                    for (int zt=0;zt<4;zt++){
                        float rv = rr[zt+dz];
                        #pragma unroll
                        for (int oc=0;oc<16;oc++) acc[zt][oc] = fmaf(rv, wv[oc], acc[zt][oc]);
                    }
                }
            }
        }
    }
    int pbase = x*HH2 + y*HH + z0;
    #pragma unroll
    for (int oc=0;oc<16;oc++){
        float* op = out + (size_t)(n*16+oc)*HH3 + pbase;
        #pragma unroll
        for (int zt=0;zt<4;zt++)
            if (z0+zt < 33) op[zt] = acc[zt][oc];
    }
}

// ---------------- conv2: grouped 2 x (8->8), DIM=66, z-tiled x4 (no BN epilogue) ----------------
// grid: (579, NG*2), block 128. blockIdx.y = n*2+g.
__global__ void k_conv2z(const float* __restrict__ in, float* __restrict__ out)
{
    int t = blockIdx.x*blockDim.x + threadIdx.x;
    int n = blockIdx.y >> 1;
    int g = blockIdx.y & 1;
    if (t >= 74052) return;
    int tz = t % 17;
    int y = (t / 17) % 66;
    int x = t / 1122;
    int z0 = tz*4;

    float acc[4][8];
    #pragma unroll
    for (int zt=0;zt<4;zt++)
        #pragma unroll
        for (int oc=0;oc<8;oc++) acc[zt][oc]=0.f;

    const float* ib = in + (size_t)(n*16 + g*8)*FF3;
    const float* wg = g_w2t + g*(8*27*8);
    #pragma unroll
    for (int ic=0; ic<8; ic++){
        const float* ip = ib + (size_t)ic*FF3;
        const float* wic = wg + ic*27*8;
        #pragma unroll
        for (int dx=0;dx<3;dx++){
            int xi = x+dx-1; if ((unsigned)xi >= 66u) continue;
            #pragma unroll
            for (int dy=0;dy<3;dy++){
                int yi = y+dy-1; if ((unsigned)yi >= 66u) continue;
                const float* rp = ip + xi*FF2 + yi*FF;
                float rr[6];
                #pragma unroll
                for (int j=0;j<6;j++){
                    int zz = z0-1+j;
                    rr[j] = ((unsigned)zz < 66u) ? __ldg(rp+zz) : 0.f;
                }
                const float4* wq = (const float4*)(wic + (dx*3+dy)*24);
                #pragma unroll
                for (int dz=0;dz<3;dz++){
                    float4 w0 = wq[dz*2+0], w1 = wq[dz*2+1];
                    float wv[8] = {w0.x,w0.y,w0.z,w0.w, w1.x,w1.y,w1.z,w1.w};
                    #pragma unroll
                    for (int zt=0;zt<4;zt++){
                        float rv = rr[zt+dz];
                        #pragma unroll
                        for (int oc=0;oc<8;oc++) acc[zt][oc] = fmaf(rv, wv[oc], acc[zt][oc]);
                    }
                }
            }
        }
    }
    int pbase = x*FF2 + y*FF + z0;
    #pragma unroll
    for (int oc=0;oc<8;oc++){
        float* op = out + (size_t)(n*16 + g*8 + oc)*FF3 + pbase;
        #pragma unroll
        for (int zt=0;zt<4;zt++)
            if (z0+zt < 66) op[zt] = acc[zt][oc];
    }
}

// ---------------- BN stats, 2-stage, C channels (measured-good path) ----------------
__global__ void k_bnpart(const float* __restrict__ buf, int C, int S)
{
    int c = blockIdx.y, chunk = blockIdx.x;
    double s = 0.0, s2 = 0.0;
    for (int n = 0; n < NG; n++){
        const float* bp = buf + (size_t)(n*C+c)*S;
        for (int p = chunk*blockDim.x + threadIdx.x; p < S; p += 32*blockDim.x){
            float v = __ldg(bp + p);
            s += v; s2 += (double)v*(double)v;
        }
    }
    __shared__ double sh[256], sh2[256];
    sh[threadIdx.x] = s; sh2[threadIdx.x] = s2;
    __syncthreads();
    for (int off = 128; off > 0; off >>= 1){
        if (threadIdx.x < off){ sh[threadIdx.x] += sh[threadIdx.x+off]; sh2[threadIdx.x] += sh2[threadIdx.x+off]; }
        __syncthreads();
    }
    if (threadIdx.x == 0){
        g_part[(c*32+chunk)*2]   = sh[0];
        g_part[(c*32+chunk)*2+1] = sh2[0];
    }
}

__global__ void k_bnfin(const float* __restrict__ g1, const float* __restrict__ b1,
                        const float* __restrict__ g2, const float* __restrict__ b2, int S)
{
    int c = threadIdx.x;
    if (c >= 16) return;
    double s = 0.0, s2 = 0.0;
    for (int k=0;k<32;k++){ s += g_part[(c*32+k)*2]; s2 += g_part[(c*32+k)*2+1]; }
    double cnt = (double)NG * (double)S;
    double mean = s/cnt;
    double var = s2/cnt - mean*mean;
    float gg = (c < 8) ? g1[c] : g2[c-8];
    float bb = (c < 8) ? b1[c] : b2[c-8];
    float sc = gg * rsqrtf((float)var + 1e-5f);
    g_scale[c] = sc;
    g_shift[c] = bb - (float)mean * sc;
}

// ---------------- BN+ReLU fused into 2x trilinear upsample (16ch) ----------------
__global__ void k_upsample(const float* __restrict__ in, float* __restrict__ out)
{
    long long t = (long long)blockIdx.x*blockDim.x + threadIdx.x;
    if (t >= (long long)NG*16*FF3) return;
    int nc = (int)(t / FF3), p = (int)(t % FF3);
    int c = nc & 15;
    int X = p / FF2, Y = (p / FF) % FF, Z = p % FF;
    const float step = 32.0f/65.0f;
    float sx = X*step; int x0 = (int)floorf(sx); float wx = sx - (float)x0; int x1 = min(x0+1, 32);
    float sy = Y*step; int y0 = (int)floorf(sy); float wy = sy - (float)y0; int y1 = min(y0+1, 32);
    float sz = Z*step; int z0 = (int)floorf(sz); float wz = sz - (float)z0; int z1 = min(z0+1, 32);
    float sc = g_scale[c], sh = g_shift[c];
    const float* ip = in + (size_t)nc*HH3;
    #define RD(a,b,cc) fmaxf(__ldg(ip+(a)*HH2+(b)*HH+(cc))*sc+sh, 0.f)
    float c00 = RD(x0,y0,z0)*(1.f-wx) + RD(x1,y0,z0)*wx;
    float c10 = RD(x0,y1,z0)*(1.f-wx) + RD(x1,y1,z0)*wx;
    float c01 = RD(x0,y0,z1)*(1.f-wx) + RD(x1,y0,z1)*wx;
    float c11 = RD(x0,y1,z1)*(1.f-wx) + RD(x1,y1,z1)*wx;
    #undef RD
    float a0 = c00*(1.f-wy) + c10*wy;
    float a1 = c01*(1.f-wy) + c11*wy;
    out[t] = a0*(1.f-wz) + a1*wz;
}

// ---------------- merged head: BN+ReLU + both 1x1 convs ----------------
__global__ void k_head(const float* __restrict__ c2,
                       const float* __restrict__ wphi, const float* __restrict__ bphi,
                       const float* __restrict__ wvort, const float* __restrict__ bvort,
                       const float* __restrict__ phiw, const float* __restrict__ vortw,
                       float* __restrict__ helm)
{
    int t = blockIdx.x*blockDim.x + threadIdx.x;
    if (t >= NG*FF3) return;
    int n = t / FF3, p = t % FF3;
    float r[16];
    #pragma unroll
    for (int ic=0; ic<16; ic++){
        float vv = c2[(size_t)(n*16+ic)*FF3 + p]*g_scale[ic] + g_shift[ic];
        r[ic] = fmaxf(vv, 0.f);
    }
    float mp = phiw[0];
    float mv = vortw[0]*66.0f;
    {
        float a = bphi[0];
        #pragma unroll
        for (int ic=0; ic<8; ic++) a = fmaf(r[ic], wphi[ic], a);
        helm[(size_t)(n*4)*FF3 + p] = a*mp;
    }
    #pragma unroll
    for (int oc=0; oc<3; oc++){
        float a = bvort[oc];
        #pragma unroll
        for (int ic=0; ic<8; ic++) a = fmaf(r[8+ic], wvort[oc*8+ic], a);
        helm[(size_t)(n*4+1+oc)*FF3 + p] = a*mv;
    }
}

// ---------------- velocity from helmholtz ----------------
__global__ void k_velocity(const float* __restrict__ helm, float* __restrict__ vel,
                           float* __restrict__ vp, float* __restrict__ vv)
{
    int t = blockIdx.x*blockDim.x + threadIdx.x;
    if (t >= NG*TS3) return;
    int n = t / TS3, p = t % TS3;
    int x = p >> 12, y = (p >> 6) & 63, z = p & 63;
    const float* phi = helm + (size_t)n*4*FF3;
    const float* s0 = phi + FF3;
    const float* s1 = phi + 2*FF3;
    const float* s2 = phi + 3*FF3;
    int X = x+1, Y = y+1, Z = z+1;
    #define IX(i,j,k) ((i)*FF2+(j)*FF+(k))
    float pu = 0.5f*(phi[IX(X,Y,z+2)] - phi[IX(X,Y,z)]);
    float pv = 0.5f*(phi[IX(X,y+2,Z)] - phi[IX(X,y,Z)]);
    float pw = 0.5f*(phi[IX(x+2,Y,Z)] - phi[IX(x,Y,Z)]);
    float u1 = (s1[IX(X+1,Y,Z)]-s1[IX(X,Y,Z)]) - (s0[IX(X,Y+1,Z)]-s0[IX(X,Y,Z)]);
    float u0 = (s1[IX(X+1,Y,z)]-s1[IX(X,Y,z)]) - (s0[IX(X,Y+1,z)]-s0[IX(X,Y,z)]);
    float vu = 0.5f*(u1+u0);
    float vA = (s0[IX(X,Y,Z+1)]-s0[IX(X,Y,Z)]) - (s2[IX(X+1,Y,Z)]-s2[IX(X,Y,Z)]);
    float vB = (s0[IX(X,y,Z+1)]-s0[IX(X,y,Z)]) - (s2[IX(X+1,y,Z)]-s2[IX(X,y,Z)]);
    float vvm = 0.5f*(vA+vB);
    float wA = (s2[IX(X,Y+1,Z)]-s2[IX(X,Y,Z)]) - (s1[IX(X,Y,Z+1)]-s1[IX(X,Y,Z)]);
    float wB = (s2[IX(x,Y+1,Z)]-s2[IX(x,Y,Z)]) - (s1[IX(x,Y,Z+1)]-s1[IX(x,Y,Z)]);
    float vw = 0.5f*(wA+wB);
    #undef IX
    size_t o = (size_t)n*3*TS3 + p;
    vp[o] = pu;          vp[o+TS3] = pv;          vp[o+2*TS3] = pw;
    vv[o] = vu;          vv[o+TS3] = vvm;         vv[o+2*TS3] = vw;
    vel[o] = pu+vu;      vel[o+TS3] = pv+vvm;     vel[o+2*TS3] = pw+vw;
}

// ---------------- advection (optionally fused with BFECC combine) ----------------
// texc == nullptr : dst = sample(src, back-trace)
// texc != nullptr : dst = 1.5*texc - 0.5*sample(src, back-trace)
__global__ void k_advect(const float* __restrict__ src, const float* __restrict__ vel,
                         float sign, const float* __restrict__ texc,
                         float* __restrict__ dst)
{
    int t = blockIdx.x*blockDim.x + threadIdx.x;
    if (t >= NG*TS3) return;
    int n = t / TS3, p = t % TS3;
    int x = p >> 12, y = (p >> 6) & 63, z = p & 63;
    size_t vb = (size_t)n*3*TS3 + p;
    float px = (float)x - sign*__ldg(vel + vb + 2*TS3);
    float py = (float)y - sign*__ldg(vel + vb + TS3);
    float pz = (float)z - sign*__ldg(vel + vb);
    px = fminf(fmaxf(px, 0.f), 63.f);
    py = fminf(fmaxf(py, 0.f), 63.f);
    pz = fminf(fmaxf(pz, 0.f), 63.f);
    int x0 = (int)floorf(px); float fx = px - (float)x0; int x1 = min(x0+1, 63);
    int y0 = (int)floorf(py); float fy = py - (float)y0; int y1 = min(y0+1, 63);
    int z0 = (int)floorf(pz); float fz = pz - (float)z0; int z1 = min(z0+1, 63);
    int b000 = (x0*64+y0)*64+z0;
    int dxo = (x1-x0)*4096, dyo = (y1-y0)*64, dzo = z1-z0;
    float w000 = (1.f-fx)*(1.f-fy)*(1.f-fz);
    float w001 = (1.f-fx)*(1.f-fy)*fz;
    float w010 = (1.f-fx)*fy*(1.f-fz);
    float w011 = (1.f-fx)*fy*fz;
    float w100 = fx*(1.f-fy)*(1.f-fz);
    float w101 = fx*(1.f-fy)*fz;
    float w110 = fx*fy*(1.f-fz);
    float w111 = fx*fy*fz;
    bool comb = (texc != nullptr);
    #pragma unroll
    for (int c=0; c<8; c++){
        size_t cbase = (size_t)(n*8+c)*TS3;
        const float* s = src + cbase;
        float r = __ldg(s+b000)*w000 + __ldg(s+b000+dzo)*w001
                + __ldg(s+b000+dyo)*w010 + __ldg(s+b000+dyo+dzo)*w011
                + __ldg(s+b000+dxo)*w100 + __ldg(s+b000+dxo+dzo)*w101
                + __ldg(s+b000+dxo+dyo)*w110 + __ldg(s+b000+dxo+dyo+dzo)*w111;
        if (comb) r = 1.5f*__ldg(texc + cbase + p) - 0.5f*r;
        dst[cbase + p] = r;
    }
}

// ---------------- LayerNorm + FFN(GELU) + residual ----------------
__global__ void k_lnffn(const float* __restrict__ pred, const float* __restrict__ lng,
                        const float* __restrict__ lnb, const float* __restrict__ w1,
                        const float* __restrict__ b1, const float* __restrict__ w2,
                        const float* __restrict__ b2, float* __restrict__ xout)
{
    __shared__ float sW1t[64*64];   // [j][i] : lng[i]*W1[i][j]
    __shared__ float sW2t[64*64];   // [c][j] : W2[j][c]
    __shared__ float sc1[64], sSg[64], sb2s[64];
    int tid = threadIdx.x;
    for (int idx = tid; idx < 4096; idx += blockDim.x){
        int r = idx >> 6, c = idx & 63;
        sW1t[c*64+r] = lng[r]*w1[idx];
        sW2t[c*64+r] = w2[idx];
    }
    __syncthreads();
    if (tid < 64){
        int j = tid;
        float a = 0.f, s = 0.f;
        for (int i=0;i<64;i++){ a += lnb[i]*w1[i*64+j]; s += sW1t[j*64+i]; }
        sc1[j] = b1[j]+a; sSg[j] = s; sb2s[j] = b2[j];
    }
    __syncthreads();
    int p = blockIdx.x*blockDim.x + tid;
    float v[64];
    float sum = 0.f;
    #pragma unroll
    for (int c=0;c<64;c++){ v[c] = pred[(size_t)c*TS3 + p]; sum += v[c]; }
    float mean = sum*(1.f/64.f);
    float s2 = 0.f;
    #pragma unroll
    for (int c=0;c<64;c++){ float d = v[c]-mean; s2 = fmaf(d,d,s2); }
    float rstd = rsqrtf(s2*(1.f/64.f) + 1e-5f);
    float h2r[64];
    for (int j=0;j<64;j++){
        const float4* wr = (const float4*)(sW1t + j*64);
        float a0=0.f,a1=0.f,a2=0.f,a3=0.f;
        #pragma unroll
        for (int i=0;i<16;i+=4){
            float4 q0 = wr[i], q1 = wr[i+1], q2 = wr[i+2], q3 = wr[i+3];
            a0 += v[4*i+0]*q0.x + v[4*i+1]*q0.y + v[4*i+2]*q0.z + v[4*i+3]*q0.w;
            a1 += v[4*i+4]*q1.x + v[4*i+5]*q1.y + v[4*i+6]*q1.z + v[4*i+7]*q1.w;
            a2 += v[4*i+8]*q2.x + v[4*i+9]*q2.y + v[4*i+10]*q2.z + v[4*i+11]*q2.w;
            a3 += v[4*i+12]*q3.x + v[4*i+13]*q3.y + v[4*i+14]*q3.z + v[4*i+15]*q3.w;
        }
        float a = (a0+a1)+(a2+a3);
        float tt = rstd*a + sc1[j] - mean*rstd*sSg[j];
        h2r[j] = 0.5f*tt*(1.f + erff(tt*0.70710678118654752f));
    }
    for (int c=0;c<64;c++){
        const float4* wr = (const float4*)(sW2t + c*64);
        float a0=0.f,a1=0.f,a2=0.f,a3=0.f;
        #pragma unroll
        for (int i=0;i<16;i+=4){
            float4 q0 = wr[i], q1 = wr[i+1], q2 = wr[i+2], q3 = wr[i+3];
            a0 += h2r[4*i+0]*q0.x + h2r[4*i+1]*q0.y + h2r[4*i+2]*q0.z + h2r[4*i+3]*q0.w;
            a1 += h2r[4*i+4]*q1.x + h2r[4*i+5]*q1.y + h2r[4*i+6]*q1.z + h2r[4*i+7]*q1.w;
            a2 += h2r[4*i+8]*q2.x + h2r[4*i+9]*q2.y + h2r[4*i+10]*q2.z + h2r[4*i+11]*q2.w;
            a3 += h2r[4*i+12]*q3.x + h2r[4*i+13]*q3.y + h2r[4*i+14]*q3.z + h2r[4*i+15]*q3.w;
        }
        xout[(size_t)c*TS3 + p] = v[c] + (a0+a1)+(a2+a3) + sb2s[c];
    }
}

// ---------------- host launch ----------------
static inline int nb(long long n, int b){ return (int)((n + b - 1) / b); }

extern "C" void kernel_launch(void* const* d_in, const int* in_sizes, int n_in,
                              void* d_out, int out_size)
{
    const float* prev      = (const float*)d_in[0];
    const float* nxt       = (const float*)d_in[1];
    const float* tex       = (const float*)d_in[2];
    const float* mask      = (const float*)d_in[3];
    const float* boundary  = (const float*)d_in[4];
    const float* enc_w     = (const float*)d_in[5];
    const float* enc_b     = (const float*)d_in[6];
    const float* phi_c1_w  = (const float*)d_in[7];
    const float* phi_bn1_g = (const float*)d_in[8];
    const float* phi_bn1_b = (const float*)d_in[9];
    const float* phi_c2_w  = (const float*)d_in[10];
    const float* phi_bn2_g = (const float*)d_in[11];
    const float* phi_bn2_b = (const float*)d_in[12];
    const float* phi_out_w = (const float*)d_in[13];
    const float* phi_out_b = (const float*)d_in[14];
    const float* vort_c1_w = (const float*)d_in[15];
    const float* vort_bn1_g= (const float*)d_in[16];
    const float* vort_bn1_b= (const float*)d_in[17];
    const float* vort_c2_w = (const float*)d_in[18];
    const float* vort_bn2_g= (const float*)d_in[19];
    const float* vort_bn2_b= (const float*)d_in[20];
    const float* vort_out_w= (const float*)d_in[21];
    const float* vort_out_b= (const float*)d_in[22];
    const float* phi_weight= (const float*)d_in[23];
    const float* vort_weight=(const float*)d_in[24];
    const float* ln_g      = (const float*)d_in[25];
    const float* ln_b      = (const float*)d_in[26];
    const float* ff_w1     = (const float*)d_in[27];
    const float* ff_b1     = (const float*)d_in[28];
    const float* ff_w2     = (const float*)d_in[29];
    const float* ff_b2     = (const float*)d_in[30];
    float* out = (float*)d_out;

    float *fpm,*fpb,*fnm,*corr,*c1,*ups,*c2,*bufA,*bufB;
    cudaGetSymbolAddress((void**)&fpm,  g_fpm);
    cudaGetSymbolAddress((void**)&fpb,  g_fpb);
    cudaGetSymbolAddress((void**)&fnm,  g_fnm);
    cudaGetSymbolAddress((void**)&corr, g_corr);
    cudaGetSymbolAddress((void**)&c1,   g_c1);
    cudaGetSymbolAddress((void**)&ups,  g_ups);
    cudaGetSymbolAddress((void**)&c2,   g_c2);
    cudaGetSymbolAddress((void**)&bufA, g_bufA);
    cudaGetSymbolAddress((void**)&bufB, g_bufB);

    // weight transposes
    k_wt1<<<nb(54*27*16,128),128>>>(phi_c1_w, vort_c1_w);
    k_wt2<<<nb(2*8*27*8,128),128>>>(phi_c2_w, vort_c2_w);

    // encoders (prev does mask+boundary in one pass)
    k_enc2<<<nb(NG*HH3,128),128>>>(prev, mask, boundary, enc_w, enc_b, fpm, fpb);
    k_enc2<<<nb(NG*HH3,128),128>>>(nxt,  mask, nullptr,  enc_w, enc_b, fnm, nullptr);

    // correlation
    k_corr<<<nb(NG*HH3,128),128>>>();

    // conv1 (54->16 merged), BN1 (separate stats), upsample
    k_conv1z<<<dim3(nb(9801,128), NG),128>>>(corr, c1);
    k_bnpart<<<dim3(32,16),256>>>(c1, 16, HH3);
    k_bnfin<<<1,16>>>(phi_bn1_g, phi_bn1_b, vort_bn1_g, vort_bn1_b, HH3);
    k_upsample<<<nb((long long)NG*16*FF3,256),256>>>(c1, ups);

    // conv2 (grouped 2x 8->8), BN2 (separate stats), head
    k_conv2z<<<dim3(nb(74052,128), NG*2),128>>>(ups, c2);
    k_bnpart<<<dim3(32,16),256>>>(c2, 16, FF3);
    k_bnfin<<<1,16>>>(phi_bn2_g, phi_bn2_b, vort_bn2_g, vort_bn2_b, FF3);
    k_head<<<nb(NG*FF3,256),256>>>(c2, phi_out_w, phi_out_b, vort_out_w, vort_out_b,
                                   phi_weight, vort_weight, out+OHELM);

    // velocities
    k_velocity<<<nb(NG*TS3,256),256>>>(out+OHELM, out+OVEL, out+OVP, out+OVV);

    // BFECC (combine fused into 2nd advect)
    k_advect<<<nb(NG*TS3,256),256>>>(tex,  out+OVEL,  1.0f, nullptr, bufA);  // phi1
    k_advect<<<nb(NG*TS3,256),256>>>(bufA, out+OVEL, -1.0f, tex,     bufB);  // 1.5 tex - 0.5 phi2
    k_advect<<<nb(NG*TS3,256),256>>>(bufB, out+OVEL,  1.0f, nullptr, bufA);  // pred

    // LN + FFN + residual
    k_lnffn<<<2048,128>>>(bufA, ln_g, ln_b, ff_w1, ff_b1, ff_w2, ff_b2, out+OX);
}